// round 5
// baseline (speedup 1.0000x reference)
#include <cuda_runtime.h>
#include <cuda_bf16.h>
#include <math.h>

// Problem constants
#define SQ 256
#define NB 64
#define NH 512
#define OUT_SEQ (SQ*NB*2*NH)   // 16,777,216 floats of [S,B,2H]; hidd follows

// ---------------- device scratch (no allocs allowed) ----------------
// P[d][gate][t][j][b]  : x-side projections + bias  (201 MB)
__device__ float dP[2u*3u*SQ*NH*NB];
// Y0[d][t][j][b]       : layer-0 outputs, transposed for layer-1 proj B-loads
__device__ float dY0T[2u*SQ*NH*NB];
// hT[d][j][b], uT[d][j][b]
__device__ float dHT[2*NH*NB];
__device__ float dUT[2*NH*NB];
__device__ unsigned gBarCnt[2];
__device__ volatile unsigned gBarGen[2];

// Per-direction global barrier over 64 CTAs. Sense-free generation counter.
// __threadfence() (scope gpu >= cluster) emits CCTL.IVALL on sm_103a ->
// L1D invalidated, so post-barrier plain LDGs see other SMs' stores.
__device__ __forceinline__ void gbar(int d) {
    __syncthreads();
    if (threadIdx.x == 0) {
        __threadfence();
        unsigned gen = gBarGen[d];
        unsigned prev = atomicAdd(&gBarCnt[d], 1u);
        if (prev == 63u) {
            gBarCnt[d] = 0u;
            __threadfence();
            gBarGen[d] = gen + 1u;
        } else {
            while (gBarGen[d] == gen) { }
        }
        __threadfence();
    }
    __syncthreads();
}

__device__ __forceinline__ float sigf(float x) { return 1.0f / (1.0f + expf(-x)); }

__device__ __forceinline__ void fma4(float a, const float4& b, float4& c) {
    c.x += a * b.x; c.y += a * b.y; c.z += a * b.z; c.w += a * b.w;
}

// Shared memory union layout (floats):
//  proj phase:   As[16][132] at 0 (2112), Bs[16][68] at 2112 (1088)
//  recur phase:  sWrzT[512][16] at 0 (8192), sWsT[512][8] at 8192 (4096),
//                sZ[8][64] at 12288, sHold[8][64] at 12800, sRed[16384] at 13312
#define SMEM_FLOATS 29696

__global__ void __launch_bounds__(256, 1)
bigru_kernel(const int*   __restrict__ tokens,
             const float* __restrict__ emb,
             const float* __restrict__ Wr,
             const float* __restrict__ Wz,
             const float* __restrict__ Ws,
             const float* __restrict__ br,
             const float* __restrict__ bz,
             const float* __restrict__ bs,
             float*       __restrict__ out)
{
    extern __shared__ float smem[];
    __shared__ int sTok[64];

    const int tid = threadIdx.x;
    const int d   = blockIdx.x >> 6;   // direction 0/1
    const int c   = blockIdx.x & 63;   // cta within direction
    const int J0  = c * 8;             // owned hidden-unit slice

    float* HT = dHT + d * (NH*NB);
    float* UT = dUT + d * (NH*NB);
    float* P  = dP   + (size_t)d * 3u * SQ * NH * NB;
    float* Y0 = dY0T + (size_t)d * SQ * NH * NB;

    float* As    = smem;            // proj
    float* Bs    = smem + 2112;     // proj
    float* sWrzT = smem;            // recur  [k*16 + row], rows 0-7=r, 8-15=z
    float* sWsT  = smem + 8192;     // recur  [k*8 + row]
    float* sZ    = smem + 12288;    // [j*64 + b]
    float* sHold = smem + 12800;    // [j*64 + b]
    float* sRed  = smem + 13312;    // reduction buffer

    for (int l = 0; l < 2; l++) {
        const int wlo = (d*2 + l) * 512;   // weight row block for (dir,layer)

        // zero own h slice (h0 = 0); visible to all after the proj-end gbar
        for (int i = tid; i < 512; i += 256) HT[J0*64 + i] = 0.0f;

        // ---------------- input projections: P[gate][t][j][b] ----------------
        // 3 gates x 4 j-tiles(128) x 256 t = 3072 tiles; 48 per CTA,
        // t innermost so the weight A-tile stays hot in L1/L2.
        for (int tb = 0; tb < 48; tb++) {
            const int tile = c * 48 + tb;
            const int t    = tile & 255;
            const int grp  = tile >> 8;     // 0..11
            const int gate = grp >> 2;
            const int jt   = grp & 3;
            const float* W = (gate == 0) ? Wr : (gate == 1) ? Wz : Ws;
            const float* Wbase = W + (size_t)(wlo + jt*128) * 1024;
            const int ty = tid >> 4, tx = tid & 15;

            if (l == 0 && tid < 64) {
                const int tp = d ? (255 - t) : t;
                sTok[tid] = tokens[tp*64 + tid];
            }

            float4 acc[8];
            #pragma unroll
            for (int r = 0; r < 8; r++) acc[r] = make_float4(0.f,0.f,0.f,0.f);

            for (int kc = 0; kc < 512; kc += 16) {
                __syncthreads();
                // A: weights 128j x 16k -> As[k][j] (transposed)
                #pragma unroll
                for (int u = 0; u < 2; u++) {
                    const int idx = tid*2 + u;          // 0..511
                    const int j = idx >> 2, kq = idx & 3;
                    const float4 v = *(const float4*)(Wbase + (size_t)j*1024 + kc + kq*4);
                    As[(kq*4+0)*132 + j] = v.x;
                    As[(kq*4+1)*132 + j] = v.y;
                    As[(kq*4+2)*132 + j] = v.z;
                    As[(kq*4+3)*132 + j] = v.w;
                }
                // B: inputs 16k x 64b -> Bs[k][b]
                if (l == 0) {
                    const int b = tid >> 2, kq = tid & 3;
                    const float4 v = *(const float4*)(emb + (size_t)sTok[b]*512 + kc + kq*4);
                    Bs[(kq*4+0)*68 + b] = v.x;
                    Bs[(kq*4+1)*68 + b] = v.y;
                    Bs[(kq*4+2)*68 + b] = v.z;
                    Bs[(kq*4+3)*68 + b] = v.w;
                } else {
                    const int k = tid >> 4, b4 = (tid & 15) * 4;
                    *(float4*)(Bs + k*68 + b4) =
                        *(const float4*)(Y0 + ((size_t)t*512 + kc + k)*64 + b4);
                }
                __syncthreads();
                #pragma unroll
                for (int k = 0; k < 16; k++) {
                    const float4 a0 = *(const float4*)(As + k*132 + ty*8);
                    const float4 a1 = *(const float4*)(As + k*132 + ty*8 + 4);
                    const float4 bq = *(const float4*)(Bs + k*68 + tx*4);
                    const float ar[8] = {a0.x,a0.y,a0.z,a0.w,a1.x,a1.y,a1.z,a1.w};
                    #pragma unroll
                    for (int r = 0; r < 8; r++) fma4(ar[r], bq, acc[r]);
                }
            }
            // epilogue: add bias, store P[t][j][b] (b-contiguous, coalesced)
            const float* bias = ((gate==0) ? br : (gate==1) ? bz : bs) + wlo + jt*128 + ty*8;
            float* Pout = P + (((size_t)gate*256 + t)*512 + jt*128 + ty*8)*64 + tx*4;
            #pragma unroll
            for (int r = 0; r < 8; r++) {
                const float bb = bias[r];
                float4 o = acc[r];
                o.x += bb; o.y += bb; o.z += bb; o.w += bb;
                *(float4*)(Pout + (size_t)r*64) = o;
            }
        }
        __syncthreads();

        // ---------------- load recurrence weights into smem ----------------
        for (int idx = tid; idx < 8192; idx += 256) {           // sWrzT[k*16+row]
            const int k = idx >> 4, row = idx & 15;
            const float* W = (row < 8) ? Wr : Wz;
            sWrzT[idx] = W[(size_t)(wlo + J0 + (row & 7))*1024 + 512 + k];
        }
        for (int idx = tid; idx < 4096; idx += 256) {           // sWsT[k*8+row]
            const int k = idx >> 3, row = idx & 7;
            sWsT[idx] = Ws[(size_t)(wlo + J0 + row)*1024 + 512 + k];
        }
        gbar(d);   // proj done, h zeros + P visible everywhere

        // ---------------- recurrence over time ----------------
        for (int t = 0; t < 256; t++) {
            // ---- rz GEMV: 16 rows (r:0-7, z:8-15) x 64 b, K=512 split 16x32 ----
            {
                const int ks = tid >> 4, pos = tid & 15;
                const int rg = pos >> 2, bg = pos & 3;
                float4 acc[4][4];
                #pragma unroll
                for (int r = 0; r < 4; r++)
                    #pragma unroll
                    for (int q = 0; q < 4; q++) acc[r][q] = make_float4(0.f,0.f,0.f,0.f);
                const int k0 = ks * 32;
                for (int k = k0; k < k0 + 32; k++) {
                    const float4 w = *(const float4*)(sWrzT + k*16 + rg*4);
                    const float wr[4] = {w.x, w.y, w.z, w.w};
                    float4 hv[4];
                    #pragma unroll
                    for (int q = 0; q < 4; q++)
                        hv[q] = *(const float4*)(HT + k*64 + bg*16 + q*4);
                    #pragma unroll
                    for (int r = 0; r < 4; r++)
                        #pragma unroll
                        for (int q = 0; q < 4; q++) fma4(wr[r], hv[q], acc[r][q]);
                }
                float* pr = sRed + (ks*16 + rg*4)*64 + bg*16;
                #pragma unroll
                for (int r = 0; r < 4; r++)
                    #pragma unroll
                    for (int q = 0; q < 4; q++)
                        *(float4*)(pr + r*64 + q*4) = acc[r][q];
            }
            __syncthreads();
            // ---- rz reduce + sigmoid; u = r*h to global, z & h_old to smem ----
            {
                const int row = tid >> 4;            // 0..15
                const int b4  = (tid & 15) * 4;
                float4 s = make_float4(0.f,0.f,0.f,0.f);
                #pragma unroll
                for (int ks = 0; ks < 16; ks++) {
                    const float4 v = *(const float4*)(sRed + (ks*16 + row)*64 + b4);
                    s.x += v.x; s.y += v.y; s.z += v.z; s.w += v.w;
                }
                const int gate = row >> 3, j = row & 7;
                const float4 pre = *(const float4*)(P + (((size_t)gate*256 + t)*512 + J0 + j)*64 + b4);
                float4 g;
                g.x = sigf(pre.x + s.x); g.y = sigf(pre.y + s.y);
                g.z = sigf(pre.z + s.z); g.w = sigf(pre.w + s.w);
                if (gate == 0) {
                    const float4 h = *(const float4*)(HT + (J0 + j)*64 + b4);
                    *(float4*)(sHold + j*64 + b4) = h;
                    float4 u;
                    u.x = g.x*h.x; u.y = g.y*h.y; u.z = g.z*h.z; u.w = g.w*h.w;
                    *(float4*)(UT + (J0 + j)*64 + b4) = u;
                } else {
                    *(float4*)(sZ + j*64 + b4) = g;
                }
            }
            gbar(d);   // u visible to all CTAs
            // ---- s GEMV: 8 rows x 64 b, K=512 split 32x16 ----
            {
                const int ks = tid >> 3, pos = tid & 7;
                const int rg = pos >> 2, bg = pos & 3;
                float4 acc[4][4];
                #pragma unroll
                for (int r = 0; r < 4; r++)
                    #pragma unroll
                    for (int q = 0; q < 4; q++) acc[r][q] = make_float4(0.f,0.f,0.f,0.f);
                const int k0 = ks * 16;
                for (int k = k0; k < k0 + 16; k++) {
                    const float4 w = *(const float4*)(sWsT + k*8 + rg*4);
                    const float wr[4] = {w.x, w.y, w.z, w.w};
                    float4 uv[4];
                    #pragma unroll
                    for (int q = 0; q < 4; q++)
                        uv[q] = *(const float4*)(UT + k*64 + bg*16 + q*4);
                    #pragma unroll
                    for (int r = 0; r < 4; r++)
                        #pragma unroll
                        for (int q = 0; q < 4; q++) fma4(wr[r], uv[q], acc[r][q]);
                }
                float* pr = sRed + (ks*8 + rg*4)*64 + bg*16;
                #pragma unroll
                for (int r = 0; r < 4; r++)
                    #pragma unroll
                    for (int q = 0; q < 4; q++)
                        *(float4*)(pr + r*64 + q*4) = acc[r][q];
            }
            __syncthreads();
            // ---- s reduce + tanh + h update + outputs ----
            {
                const int row = tid >> 5;            // 0..7
                const int b2  = (tid & 31) * 2;
                float sx = 0.f, sy = 0.f;
                #pragma unroll
                for (int ks = 0; ks < 32; ks++) {
                    const float2 v = *(const float2*)(sRed + (ks*8 + row)*64 + b2);
                    sx += v.x; sy += v.y;
                }
                const float2 pre = *(const float2*)(P + (((size_t)2*256 + t)*512 + J0 + row)*64 + b2);
                const float ssx = tanhf(pre.x + sx);
                const float ssy = tanhf(pre.y + sy);
                const float2 z = *(const float2*)(sZ    + row*64 + b2);
                const float2 h = *(const float2*)(sHold + row*64 + b2);
                const float hnx = z.x*h.x + (1.f - z.x)*ssx;
                const float hny = z.y*h.y + (1.f - z.y)*ssy;
                *(float2*)(HT + (J0 + row)*64 + b2) = make_float2(hnx, hny);
                if (l == 0) {
                    *(float2*)(Y0 + ((size_t)t*512 + J0 + row)*64 + b2) = make_float2(hnx, hny);
                } else {
                    out[((size_t)t*64 + b2    )*1024 + d*512 + J0 + row] = hnx;
                    out[((size_t)t*64 + b2 + 1)*1024 + d*512 + J0 + row] = hny;
                }
                if (t == 255) {   // final hidden states -> hidd[d*2+l][b][j]
                    out[(size_t)OUT_SEQ + ((size_t)((d*2+l)*64) + b2    )*512 + J0 + row] = hnx;
                    out[(size_t)OUT_SEQ + ((size_t)((d*2+l)*64) + b2 + 1)*512 + J0 + row] = hny;
                }
            }
            gbar(d);   // h (and Y0) visible for next step / next layer
        }
    }
}

extern "C" void kernel_launch(void* const* d_in, const int* in_sizes, int n_in,
                              void* d_out, int out_size) {
    const int*   tokens = (const int*)  d_in[0];
    const float* emb    = (const float*)d_in[1];
    const float* Wr     = (const float*)d_in[2];
    const float* Wz     = (const float*)d_in[3];
    const float* Ws     = (const float*)d_in[4];
    const float* br     = (const float*)d_in[5];
    const float* bz     = (const float*)d_in[6];
    const float* bs     = (const float*)d_in[7];
    float* out = (float*)d_out;

    cudaFuncSetAttribute(bigru_kernel,
                         cudaFuncAttributeMaxDynamicSharedMemorySize,
                         SMEM_FLOATS * sizeof(float));
    bigru_kernel<<<128, 256, SMEM_FLOATS * sizeof(float)>>>(
        tokens, emb, Wr, Wz, Ws, br, bz, bs, out);
}